// round 16
// baseline (speedup 1.0000x reference)
#include <cuda_runtime.h>
#include <cuda_bf16.h>

// BPMLL loss, factorized:
//   inner[b]  = (sum_{t==0} exp(x)) * (sum_{t==1} exp(-x))
//   length[b] = n_pos * n_neg
//   out       = sum_b inner[b] / length[b]
//
// B = 128, L = 1024, target int32.
//
// FINAL (= R8, campaign best across 15 rounds; samples 6.59/6.62/6.88us,
// ncu kernel 5.06/5.31/5.50us). One warp per row, grid = 128 x 32 (one
// warp per SM, single wave). Each lane front-batches 8 x (float4 + int4)
// loads (16 outstanding LDG.128 -> full MLP), float exp-sums with
// branchless __expf, integer n_pos (targets are 0/1). Reduce = two
// interleaved f32 shfl chains + one REDUX.SUM.U32. No __syncthreads, no
// smem. Finish: single u64 fixed-point atomic per row (low 56 bits = 2^32
// fixed-point loss sum, high 8 bits = arrival counter); the last arriver
// reads the total from the atomic return value. Integer adds everywhere ->
// bit-deterministic across graph replays (rel_err 0.0 on every run).
//
// Perf model (validated): ~4.5us fixed launch/ramp overhead + ~0.5us work;
// DRAM ~2.5%, all pipes <1%, noise +-0.3us. Overhead-bound. Axes tested
// and exhausted: kernel count, block shape (32-1024 thr, 16-128 CTAs),
// atomic topology (1/8/16/128-way, spread-address), fences/trees, warp
// reduce style (shfl / ballot / REDUX / fixed-point), mainloop op trims.
// None separate from noise; this source holds the best observed samples.

__device__ unsigned long long g_acc = 0ULL;

#define CNT_ONE   (1ULL << 56)
#define VAL_MASK  (CNT_ONE - 1ULL)
#define FP_SCALE  4294967296.0   // 2^32

__global__ void __launch_bounds__(32, 1)
bpmll_warp_kernel(const float* __restrict__ inp,
                  const int* __restrict__ tgt,
                  float* __restrict__ out,
                  int L, int B) {
    const int b   = blockIdx.x;
    const int lid = threadIdx.x;   // 0..31
    const float4* __restrict__ x4 = (const float4*)(inp + (size_t)b * L);
    const int4*   __restrict__ t4 = (const int4*)(tgt + (size_t)b * L);

    // L=1024 -> 256 float4 per row -> 8 per lane. Front-batch all loads.
    float4 v[8];
    int4   t[8];
    #pragma unroll
    for (int k = 0; k < 8; ++k) {
        v[k] = x4[lid + 32 * k];
        t[k] = t4[lid + 32 * k];
    }

    float s_neg  = 0.0f;   // sum exp(x) over negatives
    float s_pinv = 0.0f;   // sum exp(-x) over positives
    unsigned int np = 0u;  // positives count (targets are 0/1)

    #pragma unroll
    for (int k = 0; k < 8; ++k) {
        {
            bool p = (t[k].x == 1); float e = __expf(p ? -v[k].x : v[k].x);
            s_pinv += p ? e : 0.0f; s_neg += p ? 0.0f : e; np += (unsigned)t[k].x;
        }
        {
            bool p = (t[k].y == 1); float e = __expf(p ? -v[k].y : v[k].y);
            s_pinv += p ? e : 0.0f; s_neg += p ? 0.0f : e; np += (unsigned)t[k].y;
        }
        {
            bool p = (t[k].z == 1); float e = __expf(p ? -v[k].z : v[k].z);
            s_pinv += p ? e : 0.0f; s_neg += p ? 0.0f : e; np += (unsigned)t[k].z;
        }
        {
            bool p = (t[k].w == 1); float e = __expf(p ? -v[k].w : v[k].w);
            s_pinv += p ? e : 0.0f; s_neg += p ? 0.0f : e; np += (unsigned)t[k].w;
        }
    }

    // n_pos: single-instruction integer warp reduction
    np = __reduce_add_sync(0xffffffffu, np);

    // two interleaved f32 shfl-xor chains
    #pragma unroll
    for (int off = 16; off > 0; off >>= 1) {
        s_neg  += __shfl_xor_sync(0xffffffffu, s_neg,  off);
        s_pinv += __shfl_xor_sync(0xffffffffu, s_pinv, off);
    }

    if (lid == 0) {
        float fnp = (float)np;
        float fnn = (float)L - fnp;
        float loss = (s_neg * s_pinv) / (fnp * fnn);

        unsigned long long myval =
            (unsigned long long)llrint((double)loss * FP_SCALE) + CNT_ONE;
        unsigned long long old = atomicAdd(&g_acc, myval);

        if ((old >> 56) == (unsigned long long)(B - 1)) {
            unsigned long long total = (old + myval) & VAL_MASK;
            out[0] = (float)((double)total * (1.0 / FP_SCALE));
            g_acc = 0ULL;   // reset for next graph replay
        }
    }
}

extern "C" void kernel_launch(void* const* d_in, const int* in_sizes, int n_in,
                              void* d_out, int out_size) {
    const float* inp = (const float*)d_in[0];
    const int*   tgt = (const int*)d_in[1];
    float* out = (float*)d_out;

    const int B = 128;
    const int L = in_sizes[0] / B;   // 1024

    bpmll_warp_kernel<<<B, 32>>>(inp, tgt, out, L, B);
}

// round 17
// speedup vs baseline: 1.0386x; 1.0386x over previous
#include <cuda_runtime.h>
#include <cuda_bf16.h>

// BPMLL loss, factorized:
//   inner[b]  = (sum_{t==0} exp(x)) * (sum_{t==1} exp(-x))
//   length[b] = n_pos * n_neg
//   out       = sum_b inner[b] / length[b]
//
// B = 128, L = 1024, target int32.
//
// R17 = R8 (campaign best) with the FP64 packing tail removed: the per-CTA
// exit path previously did (double)loss * 2^32 + llrint (DMUL + D2L on the
// slow FP64 pipe, ~100-150 serial cycles before the completion-gating
// atomic). Now all-float: __fdividef + __float2ull_rn(loss * 2^32f).
// The loss only carries float precision anyway, so accuracy is unchanged
// (~1e-7 relative quantization). Integer accumulation in the packed u64
// atomic is unchanged -> bit-deterministic across graph replays.
//
// Structure (validated over 16 rounds): one warp per row, 128 x 32, lane
// front-batches 8 x (float4 + int4) loads (16 outstanding LDG.128),
// branchless __expf, REDUX.SUM.U32 for n_pos, two interleaved shfl chains,
// no BAR/smem; single packed u64 atomic finish (low 56 bits = fixed-point
// sum, high 8 bits = arrival counter), last arriver stores the result.

__device__ unsigned long long g_acc = 0ULL;

#define CNT_ONE   (1ULL << 56)
#define VAL_MASK  (CNT_ONE - 1ULL)
#define FP_SCALEF 4294967296.0f   // 2^32 (float)
#define INV_SCALE (1.0 / 4294967296.0)

__global__ void __launch_bounds__(32, 1)
bpmll_warp_kernel(const float* __restrict__ inp,
                  const int* __restrict__ tgt,
                  float* __restrict__ out,
                  int L, int B) {
    const int b   = blockIdx.x;
    const int lid = threadIdx.x;   // 0..31
    const float4* __restrict__ x4 = (const float4*)(inp + (size_t)b * L);
    const int4*   __restrict__ t4 = (const int4*)(tgt + (size_t)b * L);

    // L=1024 -> 256 float4 per row -> 8 per lane. Front-batch all loads.
    float4 v[8];
    int4   t[8];
    #pragma unroll
    for (int k = 0; k < 8; ++k) {
        v[k] = x4[lid + 32 * k];
        t[k] = t4[lid + 32 * k];
    }

    float s_neg  = 0.0f;   // sum exp(x) over negatives
    float s_pinv = 0.0f;   // sum exp(-x) over positives
    unsigned int np = 0u;  // positives count (targets are 0/1)

    #pragma unroll
    for (int k = 0; k < 8; ++k) {
        {
            bool p = (t[k].x == 1); float e = __expf(p ? -v[k].x : v[k].x);
            s_pinv += p ? e : 0.0f; s_neg += p ? 0.0f : e; np += (unsigned)t[k].x;
        }
        {
            bool p = (t[k].y == 1); float e = __expf(p ? -v[k].y : v[k].y);
            s_pinv += p ? e : 0.0f; s_neg += p ? 0.0f : e; np += (unsigned)t[k].y;
        }
        {
            bool p = (t[k].z == 1); float e = __expf(p ? -v[k].z : v[k].z);
            s_pinv += p ? e : 0.0f; s_neg += p ? 0.0f : e; np += (unsigned)t[k].z;
        }
        {
            bool p = (t[k].w == 1); float e = __expf(p ? -v[k].w : v[k].w);
            s_pinv += p ? e : 0.0f; s_neg += p ? 0.0f : e; np += (unsigned)t[k].w;
        }
    }

    // n_pos: single-instruction integer warp reduction
    np = __reduce_add_sync(0xffffffffu, np);

    // two interleaved f32 shfl-xor chains
    #pragma unroll
    for (int off = 16; off > 0; off >>= 1) {
        s_neg  += __shfl_xor_sync(0xffffffffu, s_neg,  off);
        s_pinv += __shfl_xor_sync(0xffffffffu, s_pinv, off);
    }

    if (lid == 0) {
        float fnp = (float)np;
        float fnn = (float)L - fnp;
        // all-float tail: no FP64 on the completion-gating path
        float loss = __fdividef(s_neg * s_pinv, fnp * fnn);

        unsigned long long myval =
            (unsigned long long)__float2ull_rn(loss * FP_SCALEF) + CNT_ONE;
        unsigned long long old = atomicAdd(&g_acc, myval);

        if ((old >> 56) == (unsigned long long)(B - 1)) {
            unsigned long long total = (old + myval) & VAL_MASK;
            out[0] = (float)((double)total * INV_SCALE);
            g_acc = 0ULL;   // reset for next graph replay
        }
    }
}

extern "C" void kernel_launch(void* const* d_in, const int* in_sizes, int n_in,
                              void* d_out, int out_size) {
    const float* inp = (const float*)d_in[0];
    const int*   tgt = (const int*)d_in[1];
    float* out = (float*)d_out;

    const int B = 128;
    const int L = in_sizes[0] / B;   // 1024

    bpmll_warp_kernel<<<B, 32>>>(inp, tgt, out, L, B);
}